// round 12
// baseline (speedup 1.0000x reference)
#include <cuda_runtime.h>
#include <cstdint>

// Conv2D 15x15 valid cross-correlation, 4096x4096 fp32 -> 4082x4082 fp32.
// Banded-Toeplitz implicit GEMM, legacy mma.sync m16n8k8 tf32 (sm_80 PTX).
//
// R12: feed-path rework.
//  - A smem layout: 16-col interleave cp = (c&~15)|4(c&3)|((c>>2)&3) so one
//    LDS.128 per row per 16-col group yields BOTH chunk fragments
//    (k,k+4,k+8,k+12). APITCH=48 (=16 mod 32 words): consecutive rows use
//    opposite bank halves -> conflict-free LDS.128. 12 A loads/ky (was 24).
//  - Division-free fills: A by row-strips (warp = row mod 4, lane = col,
//    permutation loop-invariant); B with pow2 index decode per explicit ky.
// Warp tile 32(oy) x 32(ox), CTA 128x32, K=48 (6 chunks), 24 MMAs/ky/warp,
// B deduped: 3 8x8 Toeplitz blocks per ky feed all (mt,nt).

#define H_IN  4096
#define W_IN  4096
#define KH    15
#define KW    15
#define OH    (H_IN - KH + 1)   // 4082
#define OW    (W_IN - KW + 1)   // 4082

#define TM    128               // oy per CTA
#define TN    32                // ox per CTA
#define KDIM  48                // input cols per tile
#define AROWS (TM + KH - 1)     // 142
#define APITCH 48               // floats (dense; 48 % 32 == 16 -> phase split)
#define NT    128

__device__ __forceinline__ uint32_t tf32r(float f) {
    uint32_t r; asm("cvt.rna.tf32.f32 %0, %1;" : "=r"(r) : "f"(f)); return r;
}

__device__ __forceinline__ void mma_tf32(float (&acc)[4],
                                         float a0, float a2,
                                         float a1, float a3, float2 b) {
    asm volatile(
        "mma.sync.aligned.m16n8k8.row.col.f32.tf32.tf32.f32 "
        "{%0,%1,%2,%3}, {%4,%5,%6,%7}, {%8,%9}, {%0,%1,%2,%3};"
        : "+f"(acc[0]), "+f"(acc[1]), "+f"(acc[2]), "+f"(acc[3])
        : "r"(__float_as_uint(a0)),      // a0: (r,   k)
          "r"(__float_as_uint(a1)),      // a1: (r+8, k)
          "r"(__float_as_uint(a2)),      // a2: (r,   k+4)
          "r"(__float_as_uint(a3)),      // a3: (r+8, k+4)
          "r"(__float_as_uint(b.x)),     // b0: (k,   n)
          "r"(__float_as_uint(b.y)));    // b1: (k+4, n)
}

__global__ __launch_bounds__(NT)
void conv15_hmma3_kernel(const float* __restrict__ X,
                         const float* __restrict__ Wt,
                         const float* __restrict__ bias,
                         float* __restrict__ out)
{
    __shared__ __align__(16) float sA[AROWS * APITCH];   // 27264 B
    __shared__ __align__(16) float sB[KH * 3 * 64];      // 11520 B

    const int tid  = threadIdx.x;
    const int warp = tid >> 5;
    const int lane = tid & 31;
    const int gx0  = blockIdx.x * TN;
    const int gy0  = blockIdx.y * TM;

    // ---- A fill: row strips, division-free, loop-invariant permute ----
    // cp(c) = (c & ~15) | 4*(c&3) | ((c>>2)&3)
    {
        const int c0  = lane;                         // 0..31
        const int cp0 = (c0 & ~15) | ((c0 & 3) << 2) | ((c0 >> 2) & 3);
        const int c1  = lane + 32;                    // 32..47 (lane < 16)
        const int cp1 = (c1 & ~15) | ((c1 & 3) << 2) | ((c1 >> 2) & 3);
        const int gxa = min(gx0 + c0, W_IN - 1);
        const int gxb = min(gx0 + c1, W_IN - 1);
        for (int r = warp; r < AROWS; r += 4) {
            const int gy = min(gy0 + r, H_IN - 1);
            const float* xr = X + (size_t)gy * W_IN;
            sA[r * APITCH + cp0] = __uint_as_float(tf32r(xr[gxa]));
            if (lane < 16)
                sA[r * APITCH + cp1] = __uint_as_float(tf32r(xr[gxb]));
        }
    }
    // ---- B fill: 15 ky x 3 jj deduped Toeplitz blocks, [n][k'] 8x8 ----
    // k' permute pairs (kl, kl+4) adjacent: kl = (kp>>1)|((kp&1)<<2)
    #pragma unroll 1
    for (int ky = 0; ky < KH; ky++) {
        const float* wr = Wt + ky * KW;
        for (int i = tid; i < 3 * 64; i += NT) {
            int jj = i >> 6, e = i & 63;
            int nl = e >> 3, kp = e & 7;
            int kl = (kp >> 1) | ((kp & 1) << 2);
            int kx = jj * 8 + kl - nl;
            float v = (kx >= 0 && kx < KW) ? wr[kx] : 0.0f;
            sB[ky * 192 + i] = __uint_as_float(tf32r(v));
        }
    }
    __syncthreads();

    float acc[2][4][4];
    #pragma unroll
    for (int mt = 0; mt < 2; mt++)
        #pragma unroll
        for (int nt = 0; nt < 4; nt++)
            #pragma unroll
            for (int f = 0; f < 4; f++) acc[mt][nt][f] = 0.0f;

    const int rA   = warp * 32 + (lane >> 2);   // fragment base row (mt=0)
    const int aoff = (lane & 3) * 4;            // float4 slot in 16-group
    const int bOff = (lane >> 2) * 8 + (lane & 3) * 2;

    #pragma unroll 1
    for (int ky = 0; ky < KH; ky++) {
        float2 Bf[3];
        #pragma unroll
        for (int jj = 0; jj < 3; jj++)
            Bf[jj] = *(const float2*)&sB[ky * 192 + jj * 64 + bOff];

        #pragma unroll
        for (int mt = 0; mt < 2; mt++) {
            const float* ap = sA + (rA + ky + mt * 16) * APITCH + aoff;
            float4 v02[3], v13[3];
            #pragma unroll
            for (int g = 0; g < 3; g++) {
                v02[g] = *(const float4*)(ap + 16 * g);
                v13[g] = *(const float4*)(ap + 8 * APITCH + 16 * g);
            }
            #pragma unroll
            for (int jj = 0; jj < 3; jj++) {
                #pragma unroll
                for (int nt = 0; nt < 4; nt++) {   // nt-inner: 4 indep chains
                    const int ch = nt + jj;
                    const int g  = ch >> 1;
                    if (ch & 1)
                        mma_tf32(acc[mt][nt], v02[g].z, v02[g].w,
                                 v13[g].z, v13[g].w, Bf[jj]);
                    else
                        mma_tf32(acc[mt][nt], v02[g].x, v02[g].y,
                                 v13[g].x, v13[g].y, Bf[jj]);
                }
            }
        }
    }

    // ---- epilogue: c0,c1 -> row r; c2,c3 -> row r+8; cols nt*8 + 2(lane&3) ----
    const float bv = bias[0];
    const int c2 = (lane & 3) * 2;
    #pragma unroll
    for (int mt = 0; mt < 2; mt++) {
        #pragma unroll
        for (int half = 0; half < 2; half++) {
            int oy = gy0 + warp * 32 + 16 * mt + (lane >> 2) + 8 * half;
            if (oy < OH) {
                #pragma unroll
                for (int nt = 0; nt < 4; nt++) {
                    int ox = gx0 + 8 * nt + c2;
                    if (ox < OW) {      // ox,OW even -> pair fits
                        float2 v;
                        v.x = acc[mt][nt][2 * half]     + bv;
                        v.y = acc[mt][nt][2 * half + 1] + bv;
                        *(float2*)&out[(size_t)oy * OW + ox] = v;
                    }
                }
            }
        }
    }
}

extern "C" void kernel_launch(void* const* d_in, const int* in_sizes, int n_in,
                              void* d_out, int out_size)
{
    const float* X    = (const float*)d_in[0];  // [4096,4096]
    const float* Wt   = (const float*)d_in[1];  // [15,15]
    const float* bias = (const float*)d_in[2];  // [1]
    float* out        = (float*)d_out;          // [4082,4082]

    dim3 grid((OW + TN - 1) / TN,    // 128
              (OH + TM - 1) / TM);   // 32
    conv15_hmma3_kernel<<<grid, NT>>>(X, Wt, bias, out);
}